// round 13
// baseline (speedup 1.0000x reference)
#include <cuda_runtime.h>
#include <stdint.h>

#define N_ITERS 40
#define BATCH   128
#define T_TOK   32768
#define BLOCK_THREADS  512
#define ROWS_PER_BLOCK 64
#define ROWS_PER_WARP  4

// Fused: each block recomputes its iteration's segment-end offsets inline
// (512B of sizes, L2-resident), then gathers 64 token rows.
// 512 threads/block. Threads 0-127 scan; threads 0-63 binary-search;
// each of the 16 warps moves 4 rows with 4 independent LDG.128 in flight.
//
// CONVERGED (final). Measured map of the design space on GB300:
//   - this shape: 188-190us kernel, 85-86% DRAM (6.8TB/s) — best
//   - MLP=8 per warp: regs 24->40, occ 63%, 191.8us (regressed)
//   - 128-row blocks: wave granularity, 193.8us (regressed)
//   - persistent 608-block single wave: per-tile __syncthreads drains
//     cross-tile MLP, DRAM 78%, 208.8us (regressed)
// The residual ~14% DRAM idle is read<->write turnaround on a 1:1
// bidirectional stream; bytes are irreducible (exact f32 permutation).
__global__ __launch_bounds__(BLOCK_THREADS) void seg_reverse_fused_kernel(
    const void* __restrict__ sizes_raw,
    const float4* __restrict__ data, float4* __restrict__ out) {
    __shared__ int s_ends[BATCH];
    __shared__ int s_src[ROWS_PER_BLOCK];
    __shared__ int s_warp[4];

    const int n    = blockIdx.y;
    const int tid  = threadIdx.x;
    const int lane = tid & 31;
    const int warp = tid >> 5;

    const int*       s32 = (const int*)sizes_raw;
    const long long* s64 = (const long long*)sizes_raw;

    // ---- inclusive scan of 128 segment sizes (threads 0-127) ----
    int v = 0;
    if (tid < BATCH) v = s32[n * BATCH + tid];
    #pragma unroll
    for (int d = 1; d < 32; d <<= 1) {
        int u = __shfl_up_sync(0xffffffffu, v, d);
        if (lane >= d) v += u;
    }
    if (tid < BATCH && lane == 31) s_warp[warp] = v;
    __syncthreads();
    int total = s_warp[0] + s_warp[1] + s_warp[2] + s_warp[3];

    if (total != T_TOK) {
        // sizes stored as int64: rescan using low word of each 8B element.
        __syncthreads();
        v = 0;
        if (tid < BATCH) v = (int)s64[(size_t)n * BATCH + tid];
        #pragma unroll
        for (int d = 1; d < 32; d <<= 1) {
            int u = __shfl_up_sync(0xffffffffu, v, d);
            if (lane >= d) v += u;
        }
        if (tid < BATCH && lane == 31) s_warp[warp] = v;
        __syncthreads();
    }

    if (tid < BATCH) {
        int add = 0;
        #pragma unroll
        for (int w = 0; w < 3; ++w) if (w < warp) add += s_warp[w];
        s_ends[tid] = v + add;
    }
    __syncthreads();

    // ---- per-row source index: searchsorted(ends, t, 'right') ----
    const int row0 = blockIdx.x * ROWS_PER_BLOCK;
    if (tid < ROWS_PER_BLOCK) {
        const int t = row0 + tid;
        int lo = 0, hi = BATCH;
        #pragma unroll
        for (int s = 0; s < 8; ++s) {   // answer in [0,128] -> 8 bisect steps
            int mid = (lo + hi) >> 1;
            if (s_ends[mid] > t) hi = mid; else lo = mid + 1;
        }
        const int seg   = (lo < BATCH) ? lo : (BATCH - 1);
        const int end   = s_ends[seg];
        const int start = seg ? s_ends[seg - 1] : 0;
        int src = start + end - 1 - t;
        src = src < 0 ? 0 : (src >= T_TOK ? T_TOK - 1 : src);
        s_src[tid] = src;
    }
    __syncthreads();

    // ---- copy: 4 independent 512B row reads in flight, then 4 writes ----
    const size_t base = (size_t)n * T_TOK;
    const int r = warp * ROWS_PER_WARP;

    float4 v0 = __ldcs(&data[(base + (size_t)s_src[r + 0]) * 32 + lane]);
    float4 v1 = __ldcs(&data[(base + (size_t)s_src[r + 1]) * 32 + lane]);
    float4 v2 = __ldcs(&data[(base + (size_t)s_src[r + 2]) * 32 + lane]);
    float4 v3 = __ldcs(&data[(base + (size_t)s_src[r + 3]) * 32 + lane]);

    const size_t o = (base + (size_t)(row0 + r)) * 32 + lane;
    __stcs(&out[o +  0], v0);
    __stcs(&out[o + 32], v1);
    __stcs(&out[o + 64], v2);
    __stcs(&out[o + 96], v3);
}

extern "C" void kernel_launch(void* const* d_in, const int* in_sizes, int n_in,
                              void* d_out, int out_size) {
    // Identify which input is `sizes` (N_ITERS*BATCH elements) vs `data`.
    const void*   sizes = d_in[0];
    const float4* data  = (const float4*)d_in[1];
    if (n_in >= 2 && in_sizes[0] != N_ITERS * BATCH) {
        sizes = d_in[1];
        data  = (const float4*)d_in[0];
    }
    float4* out = (float4*)d_out;

    dim3 grid(T_TOK / ROWS_PER_BLOCK, N_ITERS);
    seg_reverse_fused_kernel<<<grid, BLOCK_THREADS>>>(sizes, data, out);
}

// round 14
// speedup vs baseline: 1.0025x; 1.0025x over previous
#include <cuda_runtime.h>
#include <stdint.h>

#define N_ITERS 40
#define BATCH   128
#define T_TOK   32768
#define BLOCK_THREADS  512
#define ROWS_PER_BLOCK 64
#define ROWS_PER_WARP  4

// Fused: each block recomputes its iteration's segment-end offsets inline
// (512B of sizes, L2-resident), then gathers 64 token rows.
// 512 threads/block. Threads 0-127 scan; threads 0-63 binary-search;
// each of the 16 warps moves 4 rows with 4 independent LDG.128 in flight.
//
// CONVERGED (final). Measured map of the design space on GB300:
//   - this shape: 188-190us kernel, 85-86% DRAM (6.8TB/s) — best
//   - MLP=8 per warp: regs 24->40, occ 63%, 191.8us (regressed)
//   - 128-row blocks: wave granularity, 193.8us (regressed)
//   - persistent 608-block single wave: per-tile __syncthreads drains
//     cross-tile MLP, DRAM 78%, 208.8us (regressed)
// The residual ~14% DRAM idle is read<->write turnaround on a 1:1
// bidirectional stream; bytes are irreducible (exact f32 permutation) and
// the LTS cap is path-independent, so no instruction-mix change helps.
__global__ __launch_bounds__(BLOCK_THREADS) void seg_reverse_fused_kernel(
    const void* __restrict__ sizes_raw,
    const float4* __restrict__ data, float4* __restrict__ out) {
    __shared__ int s_ends[BATCH];
    __shared__ int s_src[ROWS_PER_BLOCK];
    __shared__ int s_warp[4];

    const int n    = blockIdx.y;
    const int tid  = threadIdx.x;
    const int lane = tid & 31;
    const int warp = tid >> 5;

    const int*       s32 = (const int*)sizes_raw;
    const long long* s64 = (const long long*)sizes_raw;

    // ---- inclusive scan of 128 segment sizes (threads 0-127) ----
    int v = 0;
    if (tid < BATCH) v = s32[n * BATCH + tid];
    #pragma unroll
    for (int d = 1; d < 32; d <<= 1) {
        int u = __shfl_up_sync(0xffffffffu, v, d);
        if (lane >= d) v += u;
    }
    if (tid < BATCH && lane == 31) s_warp[warp] = v;
    __syncthreads();
    int total = s_warp[0] + s_warp[1] + s_warp[2] + s_warp[3];

    if (total != T_TOK) {
        // sizes stored as int64: rescan using low word of each 8B element.
        __syncthreads();
        v = 0;
        if (tid < BATCH) v = (int)s64[(size_t)n * BATCH + tid];
        #pragma unroll
        for (int d = 1; d < 32; d <<= 1) {
            int u = __shfl_up_sync(0xffffffffu, v, d);
            if (lane >= d) v += u;
        }
        if (tid < BATCH && lane == 31) s_warp[warp] = v;
        __syncthreads();
    }

    if (tid < BATCH) {
        int add = 0;
        #pragma unroll
        for (int w = 0; w < 3; ++w) if (w < warp) add += s_warp[w];
        s_ends[tid] = v + add;
    }
    __syncthreads();

    // ---- per-row source index: searchsorted(ends, t, 'right') ----
    const int row0 = blockIdx.x * ROWS_PER_BLOCK;
    if (tid < ROWS_PER_BLOCK) {
        const int t = row0 + tid;
        int lo = 0, hi = BATCH;
        #pragma unroll
        for (int s = 0; s < 8; ++s) {   // answer in [0,128] -> 8 bisect steps
            int mid = (lo + hi) >> 1;
            if (s_ends[mid] > t) hi = mid; else lo = mid + 1;
        }
        const int seg   = (lo < BATCH) ? lo : (BATCH - 1);
        const int end   = s_ends[seg];
        const int start = seg ? s_ends[seg - 1] : 0;
        int src = start + end - 1 - t;
        src = src < 0 ? 0 : (src >= T_TOK ? T_TOK - 1 : src);
        s_src[tid] = src;
    }
    __syncthreads();

    // ---- copy: 4 independent 512B row reads in flight, then 4 writes ----
    const size_t base = (size_t)n * T_TOK;
    const int r = warp * ROWS_PER_WARP;

    float4 v0 = __ldcs(&data[(base + (size_t)s_src[r + 0]) * 32 + lane]);
    float4 v1 = __ldcs(&data[(base + (size_t)s_src[r + 1]) * 32 + lane]);
    float4 v2 = __ldcs(&data[(base + (size_t)s_src[r + 2]) * 32 + lane]);
    float4 v3 = __ldcs(&data[(base + (size_t)s_src[r + 3]) * 32 + lane]);

    const size_t o = (base + (size_t)(row0 + r)) * 32 + lane;
    __stcs(&out[o +  0], v0);
    __stcs(&out[o + 32], v1);
    __stcs(&out[o + 64], v2);
    __stcs(&out[o + 96], v3);
}

extern "C" void kernel_launch(void* const* d_in, const int* in_sizes, int n_in,
                              void* d_out, int out_size) {
    // Identify which input is `sizes` (N_ITERS*BATCH elements) vs `data`.
    const void*   sizes = d_in[0];
    const float4* data  = (const float4*)d_in[1];
    if (n_in >= 2 && in_sizes[0] != N_ITERS * BATCH) {
        sizes = d_in[1];
        data  = (const float4*)d_in[0];
    }
    float4* out = (float4*)d_out;

    dim3 grid(T_TOK / ROWS_PER_BLOCK, N_ITERS);
    seg_reverse_fused_kernel<<<grid, BLOCK_THREADS>>>(sizes, data, out);
}